// round 5
// baseline (speedup 1.0000x reference)
#include <cuda_runtime.h>

#define VOCAB   101
#define EMB     32
#define HID     32
#define T_STEPS 512

// Precomputed per-token gate contributions: tbl[v][j] = (i, f, g, o) where
// gate = sum_e emb[v][e] * Wx[e][gate*32+j] + b[gate*32+j]
__device__ float4 g_tbl[VOCAB * HID];
// Packed recurrence weights (f32x2 across k):
// g_wpk[(gate*16 + k2)*32 + j] = ( Wh[2*k2][gate*32+j], Wh[2*k2+1][gate*32+j] )
__device__ unsigned long long g_wpk[4 * 16 * 32];

__device__ __forceinline__ unsigned long long pack2(float lo, float hi) {
    unsigned long long r;
    asm("mov.b64 %0, {%1, %2};" : "=l"(r) : "f"(lo), "f"(hi));
    return r;
}
__device__ __forceinline__ float lo2(unsigned long long v) {
    return __uint_as_float((unsigned int)v);
}
__device__ __forceinline__ float hi2(unsigned long long v) {
    return __uint_as_float((unsigned int)(v >> 32));
}
// Packed double-rate fp32 FMA (Blackwell FFMA2)
__device__ __forceinline__ unsigned long long ffma2(unsigned long long a,
                                                    unsigned long long b,
                                                    unsigned long long c) {
    unsigned long long d;
    asm("fma.rn.f32x2 %0, %1, %2, %3;" : "=l"(d) : "l"(a), "l"(b), "l"(c));
    return d;
}
__device__ __forceinline__ float sigmoidf_(float x) {
    return __fdividef(1.f, 1.f + __expf(-x));
}
__device__ __forceinline__ float tanhf_(float x) {
    // 1 - 2/(e^{2x}+1); exact at +-inf overflow/underflow of expf
    float e = __expf(2.f * x);
    return 1.f - __fdividef(2.f, e + 1.f);
}

// ---------------------------------------------------------------------------
// Prep: build token->xgate table and packed Wh. Tiny (3232 dot products).
// ---------------------------------------------------------------------------
__global__ void prep_kernel(const float* __restrict__ emb,
                            const float* __restrict__ Wx,
                            const float* __restrict__ b,
                            const float* __restrict__ Wh) {
    int tid = blockIdx.x * blockDim.x + threadIdx.x;
    if (tid < VOCAB * HID) {
        int v = tid / HID, j = tid % HID;
        float si = b[j], sf = b[HID + j], sg = b[2 * HID + j], so = b[3 * HID + j];
        #pragma unroll
        for (int e = 0; e < EMB; e++) {
            float xe = emb[v * EMB + e];
            si = fmaf(xe, Wx[e * 4 * HID + j], si);
            sf = fmaf(xe, Wx[e * 4 * HID + HID + j], sf);
            sg = fmaf(xe, Wx[e * 4 * HID + 2 * HID + j], sg);
            so = fmaf(xe, Wx[e * 4 * HID + 3 * HID + j], so);
        }
        g_tbl[tid] = make_float4(si, sf, sg, so);
    }
    if (tid < 4 * 16 * 32) {
        int j  = tid & 31;
        int k2 = (tid >> 5) & 15;
        int g  = tid >> 9;
        float w0 = Wh[(2 * k2) * 4 * HID + g * HID + j];
        float w1 = Wh[(2 * k2 + 1) * 4 * HID + g * HID + j];
        g_wpk[tid] = pack2(w0, w1);
    }
}

// ---------------------------------------------------------------------------
// Main: one warp per batch row, lane j owns hidden unit j.
// Recurrence matvec in packed f32x2 (pairs across k), weights in registers.
// ---------------------------------------------------------------------------
__global__ void __launch_bounds__(256, 1)
lstm_kernel(const int* __restrict__ x,
            const float* __restrict__ Wfc,
            const float* __restrict__ bfc,
            float* __restrict__ out, int B) {
    const unsigned FULL = 0xffffffffu;
    const int lane = threadIdx.x & 31;
    const int b = (int)((blockIdx.x * blockDim.x + threadIdx.x) >> 5);
    if (b >= B) return;

    // 64 packed weight words (128 fp32) in registers
    unsigned long long w[64];
    #pragma unroll
    for (int i = 0; i < 64; i++) w[i] = g_wpk[i * 32 + lane];

    float h = 0.f, c = 0.f;
    const int* xrow = x + (long long)b * T_STEPS;

    for (int tc = 0; tc < T_STEPS / 32; ++tc) {
        int tok_r = xrow[tc * 32 + lane];   // coalesced: 32 tokens per outer iter
        #pragma unroll 4
        for (int s = 0; s < 32; ++s) {
            int tok = __shfl_sync(FULL, tok_r, s);
            float4 tb = __ldg(&g_tbl[tok * HID + lane]);  // (i,f,g,o) per lane

            // Build this lane's h pair (h_{2m}, h_{2m+1}), m = lane>>1
            float hx = __shfl_xor_sync(FULL, h, 1);
            unsigned long long hp = (lane & 1) ? pack2(hx, h) : pack2(h, hx);

            // Gate accumulators: lo = even-k partial, hi = odd-k partial
            unsigned long long a0 = pack2(tb.x, 0.f);
            unsigned long long a1 = pack2(tb.y, 0.f);
            unsigned long long a2 = pack2(tb.z, 0.f);
            unsigned long long a3 = pack2(tb.w, 0.f);

            #pragma unroll
            for (int k2 = 0; k2 < 16; ++k2) {
                // pair (h_{2k2}, h_{2k2+1}) broadcast from lane 2*k2
                unsigned long long hk = __shfl_sync(FULL, hp, 2 * k2);
                a0 = ffma2(hk, w[k2],      a0);
                a1 = ffma2(hk, w[16 + k2], a1);
                a2 = ffma2(hk, w[32 + k2], a2);
                a3 = ffma2(hk, w[48 + k2], a3);
            }
            float gi = lo2(a0) + hi2(a0);
            float gf = lo2(a1) + hi2(a1);
            float gg = lo2(a2) + hi2(a2);
            float go = lo2(a3) + hi2(a3);

            float is = sigmoidf_(gi);
            float fs = sigmoidf_(gf);
            float os = sigmoidf_(go);
            float gt = tanhf_(gg);
            c = fmaf(fs, c, is * gt);
            h = os * tanhf_(c);
        }
    }

    // FC head: out[b] = h @ W_fc + b_fc  (warp butterfly reduce, 2 outputs)
    float v0 = h * Wfc[lane * 2 + 0];
    float v1 = h * Wfc[lane * 2 + 1];
    #pragma unroll
    for (int o = 16; o; o >>= 1) {
        v0 += __shfl_xor_sync(FULL, v0, o);
        v1 += __shfl_xor_sync(FULL, v1, o);
    }
    if (lane == 0) {
        out[b * 2 + 0] = v0 + bfc[0];
        out[b * 2 + 1] = v1 + bfc[1];
    }
}

// ---------------------------------------------------------------------------
// Harness entry
// Inputs (metadata order): x[int32 B*T], emb[101*32], Wx[32*128], Wh[32*128],
//                          b[128], W_fc[32*2], b_fc[2]. Output: float [B,2].
// ---------------------------------------------------------------------------
extern "C" void kernel_launch(void* const* d_in, const int* in_sizes, int n_in,
                              void* d_out, int out_size) {
    const int*   x   = (const int*)  d_in[0];
    const float* emb = (const float*)d_in[1];
    const float* Wx  = (const float*)d_in[2];
    const float* Wh  = (const float*)d_in[3];
    const float* b   = (const float*)d_in[4];
    const float* Wfc = (const float*)d_in[5];
    const float* bfc = (const float*)d_in[6];
    float* out = (float*)d_out;

    const int B = in_sizes[0] / T_STEPS;

    prep_kernel<<<(VOCAB * HID + 255) / 256, 256>>>(emb, Wx, b, Wh);

    const int threads = 256;                  // 8 warps = 8 batch rows / block
    const int blocks  = (B * 32 + threads - 1) / threads;
    lstm_kernel<<<blocks, threads>>>(x, Wfc, bfc, out, B);
}

// round 6
// speedup vs baseline: 1.1131x; 1.1131x over previous
#include <cuda_runtime.h>

#define VOCAB   101
#define EMB     32
#define HID     32
#define T_STEPS 512
#define NWARP   8   // warps (batch rows) per block

// Precomputed per-token gate contributions: tbl[v][j] = (i, f, g, o)
__device__ float4 g_tbl[VOCAB * HID];
// Packed recurrence weights (f32x2 across k):
// g_wpk[(gate*16 + k2)*32 + j] = ( Wh[2*k2][gate*32+j], Wh[2*k2+1][gate*32+j] )
__device__ unsigned long long g_wpk[4 * 16 * 32];

__device__ __forceinline__ unsigned long long pack2(float lo, float hi) {
    unsigned long long r;
    asm("mov.b64 %0, {%1, %2};" : "=l"(r) : "f"(lo), "f"(hi));
    return r;
}
__device__ __forceinline__ float lo2(unsigned long long v) {
    return __uint_as_float((unsigned int)v);
}
__device__ __forceinline__ float hi2(unsigned long long v) {
    return __uint_as_float((unsigned int)(v >> 32));
}
// Packed double-rate fp32 FMA (Blackwell FFMA2)
__device__ __forceinline__ unsigned long long ffma2(unsigned long long a,
                                                    unsigned long long b,
                                                    unsigned long long c) {
    unsigned long long d;
    asm("fma.rn.f32x2 %0, %1, %2, %3;" : "=l"(d) : "l"(a), "l"(b), "l"(c));
    return d;
}
__device__ __forceinline__ float sigmoidf_(float x) {
    return __fdividef(1.f, 1.f + __expf(-x));
}
__device__ __forceinline__ float tanhf_(float x) {
    float e = __expf(2.f * x);
    return 1.f - __fdividef(2.f, e + 1.f);
}

// ---------------------------------------------------------------------------
// Prep: token->xgate table and packed Wh. Tiny.
// ---------------------------------------------------------------------------
__global__ void prep_kernel(const float* __restrict__ emb,
                            const float* __restrict__ Wx,
                            const float* __restrict__ b,
                            const float* __restrict__ Wh) {
    int tid = blockIdx.x * blockDim.x + threadIdx.x;
    if (tid < VOCAB * HID) {
        int v = tid / HID, j = tid % HID;
        float si = b[j], sf = b[HID + j], sg = b[2 * HID + j], so = b[3 * HID + j];
        #pragma unroll
        for (int e = 0; e < EMB; e++) {
            float xe = emb[v * EMB + e];
            si = fmaf(xe, Wx[e * 4 * HID + j], si);
            sf = fmaf(xe, Wx[e * 4 * HID + HID + j], sf);
            sg = fmaf(xe, Wx[e * 4 * HID + 2 * HID + j], sg);
            so = fmaf(xe, Wx[e * 4 * HID + 3 * HID + j], so);
        }
        g_tbl[tid] = make_float4(si, sf, sg, so);
    }
    if (tid < 4 * 16 * 32) {
        int j  = tid & 31;
        int k2 = (tid >> 5) & 15;
        int g  = tid >> 9;
        float w0 = Wh[(2 * k2) * 4 * HID + g * HID + j];
        float w1 = Wh[(2 * k2 + 1) * 4 * HID + g * HID + j];
        g_wpk[tid] = pack2(w0, w1);
    }
}

// ---------------------------------------------------------------------------
// Main: one warp per batch row, lane j owns hidden unit j.
// h broadcast via shared memory (1 STS + 8 broadcast LDS.128 per step)
// instead of 64-bit shuffles; matvec in packed f32x2, Wh in registers.
// ---------------------------------------------------------------------------
__global__ void __launch_bounds__(NWARP * 32, 1)
lstm_kernel(const int* __restrict__ x,
            const float* __restrict__ Wfc,
            const float* __restrict__ bfc,
            float* __restrict__ out, int B) {
    const unsigned FULL = 0xffffffffu;
    const int lane = threadIdx.x & 31;
    const int wid  = threadIdx.x >> 5;
    const int b = (int)(blockIdx.x * NWARP + wid);
    if (b >= B) return;

    __shared__ float4 hbuf[NWARP][8];   // 32 floats per warp, 128B aligned

    // 64 packed weight words (128 fp32) in registers
    unsigned long long w[64];
    #pragma unroll
    for (int i = 0; i < 64; i++) w[i] = g_wpk[i * 32 + lane];

    // h vector (all 32 values) replicated in each lane's registers
    float4 hv[8];
    #pragma unroll
    for (int q = 0; q < 8; q++) hv[q] = make_float4(0.f, 0.f, 0.f, 0.f);

    float h = 0.f, c = 0.f;
    const int* xrow = x + (long long)b * T_STEPS;

    for (int tc = 0; tc < T_STEPS / 32; ++tc) {
        int tok_r = xrow[tc * 32 + lane];        // coalesced token block
        #pragma unroll 4
        for (int s = 0; s < 32; ++s) {
            // issue the table load early; consumed only after the FMA loop
            int tok = __shfl_sync(FULL, tok_r, s);
            float4 tb = __ldg(&g_tbl[tok * HID + lane]);

            unsigned long long a0 = 0ull, a1 = 0ull, a2 = 0ull, a3 = 0ull;
            #pragma unroll
            for (int q = 0; q < 8; ++q) {
                unsigned long long h0 = pack2(hv[q].x, hv[q].y);
                unsigned long long h1 = pack2(hv[q].z, hv[q].w);
                a0 = ffma2(h0, w[     2 * q    ], a0);
                a0 = ffma2(h1, w[     2 * q + 1], a0);
                a1 = ffma2(h0, w[16 + 2 * q    ], a1);
                a1 = ffma2(h1, w[16 + 2 * q + 1], a1);
                a2 = ffma2(h0, w[32 + 2 * q    ], a2);
                a2 = ffma2(h1, w[32 + 2 * q + 1], a2);
                a3 = ffma2(h0, w[48 + 2 * q    ], a3);
                a3 = ffma2(h1, w[48 + 2 * q + 1], a3);
            }
            float gi = tb.x + (lo2(a0) + hi2(a0));
            float gf = tb.y + (lo2(a1) + hi2(a1));
            float gg = tb.z + (lo2(a2) + hi2(a2));
            float go = tb.w + (lo2(a3) + hi2(a3));

            float is = sigmoidf_(gi);
            float fs = sigmoidf_(gf);
            float os = sigmoidf_(go);
            float gt = tanhf_(gg);
            c = fmaf(fs, c, is * gt);
            h = os * tanhf_(c);

            // broadcast new h through shared memory
            ((float*)hbuf[wid])[lane] = h;
            __syncwarp();
            #pragma unroll
            for (int q = 0; q < 8; ++q) hv[q] = hbuf[wid][q];  // LDS.128 broadcast
        }
    }

    // FC head: out[b] = h @ W_fc + b_fc  (warp butterfly reduce, 2 outputs)
    float v0 = h * Wfc[lane * 2 + 0];
    float v1 = h * Wfc[lane * 2 + 1];
    #pragma unroll
    for (int o = 16; o; o >>= 1) {
        v0 += __shfl_xor_sync(FULL, v0, o);
        v1 += __shfl_xor_sync(FULL, v1, o);
    }
    if (lane == 0) {
        out[b * 2 + 0] = v0 + bfc[0];
        out[b * 2 + 1] = v1 + bfc[1];
    }
}

// ---------------------------------------------------------------------------
// Harness entry
// Inputs: x[int32 B*T], emb[101*32], Wx[32*128], Wh[32*128], b[128],
//         W_fc[32*2], b_fc[2]. Output: float [B,2].
// ---------------------------------------------------------------------------
extern "C" void kernel_launch(void* const* d_in, const int* in_sizes, int n_in,
                              void* d_out, int out_size) {
    const int*   x   = (const int*)  d_in[0];
    const float* emb = (const float*)d_in[1];
    const float* Wx  = (const float*)d_in[2];
    const float* Wh  = (const float*)d_in[3];
    const float* b   = (const float*)d_in[4];
    const float* Wfc = (const float*)d_in[5];
    const float* bfc = (const float*)d_in[6];
    float* out = (float*)d_out;

    const int B = in_sizes[0] / T_STEPS;

    prep_kernel<<<(VOCAB * HID + 255) / 256, 256>>>(emb, Wx, b, Wh);

    const int threads = NWARP * 32;
    const int blocks  = (B + NWARP - 1) / NWARP;
    lstm_kernel<<<blocks, threads>>>(x, Wfc, bfc, out, B);
}

// round 7
// speedup vs baseline: 1.4436x; 1.2970x over previous
#include <cuda_runtime.h>

#define VOCAB   101
#define EMB     32
#define HID     32
#define T_STEPS 512
#define NWARP   8   // warps per block; each warp handles 2 batch rows

// Precomputed per-token gate contributions: tbl[v][j] = (i, f, g, o)
__device__ float4 g_tbl[VOCAB * HID];
// Packed recurrence weights (f32x2 across k):
// g_wpk[(gate*16 + k2)*32 + j] = ( Wh[2*k2][gate*32+j], Wh[2*k2+1][gate*32+j] )
__device__ unsigned long long g_wpk[4 * 16 * 32];

__device__ __forceinline__ unsigned long long pack2(float lo, float hi) {
    unsigned long long r;
    asm("mov.b64 %0, {%1, %2};" : "=l"(r) : "f"(lo), "f"(hi));
    return r;
}
__device__ __forceinline__ float lo2(unsigned long long v) {
    return __uint_as_float((unsigned int)v);
}
__device__ __forceinline__ float hi2(unsigned long long v) {
    return __uint_as_float((unsigned int)(v >> 32));
}
// Packed double-rate fp32 FMA (Blackwell FFMA2)
__device__ __forceinline__ unsigned long long ffma2(unsigned long long a,
                                                    unsigned long long b,
                                                    unsigned long long c) {
    unsigned long long d;
    asm("fma.rn.f32x2 %0, %1, %2, %3;" : "=l"(d) : "l"(a), "l"(b), "l"(c));
    return d;
}
// HW tanh (MUFU.TANH, sm_75+): 1 MUFU op, ~1e-5 abs err
__device__ __forceinline__ float tanh_fast(float x) {
    float y;
    asm("tanh.approx.f32 %0, %1;" : "=f"(y) : "f"(x));
    return y;
}
__device__ __forceinline__ float sigmoid_fast(float x) {
    return fmaf(0.5f, tanh_fast(0.5f * x), 0.5f);
}

// ---------------------------------------------------------------------------
// Prep: token->xgate table and packed Wh. Tiny.
// ---------------------------------------------------------------------------
__global__ void prep_kernel(const float* __restrict__ emb,
                            const float* __restrict__ Wx,
                            const float* __restrict__ b,
                            const float* __restrict__ Wh) {
    int tid = blockIdx.x * blockDim.x + threadIdx.x;
    if (tid < VOCAB * HID) {
        int v = tid / HID, j = tid % HID;
        float si = b[j], sf = b[HID + j], sg = b[2 * HID + j], so = b[3 * HID + j];
        #pragma unroll
        for (int e = 0; e < EMB; e++) {
            float xe = emb[v * EMB + e];
            si = fmaf(xe, Wx[e * 4 * HID + j], si);
            sf = fmaf(xe, Wx[e * 4 * HID + HID + j], sf);
            sg = fmaf(xe, Wx[e * 4 * HID + 2 * HID + j], sg);
            so = fmaf(xe, Wx[e * 4 * HID + 3 * HID + j], so);
        }
        g_tbl[tid] = make_float4(si, sf, sg, so);
    }
    if (tid < 4 * 16 * 32) {
        int j  = tid & 31;
        int k2 = (tid >> 5) & 15;
        int g  = tid >> 9;
        float w0 = Wh[(2 * k2) * 4 * HID + g * HID + j];
        float w1 = Wh[(2 * k2 + 1) * 4 * HID + g * HID + j];
        g_wpk[tid] = pack2(w0, w1);
    }
}

// ---------------------------------------------------------------------------
// Main: one warp handles TWO batch rows (weights in registers shared across
// both). Lane j owns hidden unit j of each row. h broadcast through smem;
// recurrence matvec in packed f32x2; activations via MUFU.TANH.
// ---------------------------------------------------------------------------
__global__ void __launch_bounds__(NWARP * 32, 1)
lstm_kernel(const int* __restrict__ x,
            const float* __restrict__ Wfc,
            const float* __restrict__ bfc,
            float* __restrict__ out, int B) {
    const unsigned FULL = 0xffffffffu;
    const int lane = threadIdx.x & 31;
    const int wid  = threadIdx.x >> 5;
    const int b0 = 2 * (int)(blockIdx.x * NWARP + wid);
    if (b0 >= B) return;

    __shared__ float4 hbuf[NWARP][2][8];   // 32 floats per warp per row

    // 64 packed weight words (128 fp32) — shared across both rows
    unsigned long long w[64];
    #pragma unroll
    for (int i = 0; i < 64; i++) w[i] = g_wpk[i * 32 + lane];

    // full h vectors replicated in registers (per row)
    float4 hv0[8], hv1[8];
    #pragma unroll
    for (int q = 0; q < 8; q++) {
        hv0[q] = make_float4(0.f, 0.f, 0.f, 0.f);
        hv1[q] = make_float4(0.f, 0.f, 0.f, 0.f);
    }

    float h0 = 0.f, c0 = 0.f, h1 = 0.f, c1 = 0.f;
    const int* xrow0 = x + (long long)b0 * T_STEPS;
    const int* xrow1 = xrow0 + T_STEPS;

    for (int tc = 0; tc < T_STEPS / 32; ++tc) {
        int t0r = xrow0[tc * 32 + lane];
        int t1r = xrow1[tc * 32 + lane];
        #pragma unroll 2
        for (int s = 0; s < 32; ++s) {
            int tok0 = __shfl_sync(FULL, t0r, s);
            int tok1 = __shfl_sync(FULL, t1r, s);
            float4 tb0 = __ldg(&g_tbl[tok0 * HID + lane]);
            float4 tb1 = __ldg(&g_tbl[tok1 * HID + lane]);

            unsigned long long a00 = 0ull, a01 = 0ull, a02 = 0ull, a03 = 0ull;
            unsigned long long a10 = 0ull, a11 = 0ull, a12 = 0ull, a13 = 0ull;
            #pragma unroll
            for (int q = 0; q < 8; ++q) {
                unsigned long long p00 = pack2(hv0[q].x, hv0[q].y);
                unsigned long long p01 = pack2(hv0[q].z, hv0[q].w);
                unsigned long long p10 = pack2(hv1[q].x, hv1[q].y);
                unsigned long long p11 = pack2(hv1[q].z, hv1[q].w);
                a00 = ffma2(p00, w[     2 * q    ], a00);
                a10 = ffma2(p10, w[     2 * q    ], a10);
                a00 = ffma2(p01, w[     2 * q + 1], a00);
                a10 = ffma2(p11, w[     2 * q + 1], a10);
                a01 = ffma2(p00, w[16 + 2 * q    ], a01);
                a11 = ffma2(p10, w[16 + 2 * q    ], a11);
                a01 = ffma2(p01, w[16 + 2 * q + 1], a01);
                a11 = ffma2(p11, w[16 + 2 * q + 1], a11);
                a02 = ffma2(p00, w[32 + 2 * q    ], a02);
                a12 = ffma2(p10, w[32 + 2 * q    ], a12);
                a02 = ffma2(p01, w[32 + 2 * q + 1], a02);
                a12 = ffma2(p11, w[32 + 2 * q + 1], a12);
                a03 = ffma2(p00, w[48 + 2 * q    ], a03);
                a13 = ffma2(p10, w[48 + 2 * q    ], a13);
                a03 = ffma2(p01, w[48 + 2 * q + 1], a03);
                a13 = ffma2(p11, w[48 + 2 * q + 1], a13);
            }
            // row 0 gates + update
            {
                float gi = tb0.x + (lo2(a00) + hi2(a00));
                float gf = tb0.y + (lo2(a01) + hi2(a01));
                float gg = tb0.z + (lo2(a02) + hi2(a02));
                float go = tb0.w + (lo2(a03) + hi2(a03));
                float is = sigmoid_fast(gi);
                float fs = sigmoid_fast(gf);
                float os = sigmoid_fast(go);
                float gt = tanh_fast(gg);
                c0 = fmaf(fs, c0, is * gt);
                h0 = os * tanh_fast(c0);
            }
            // row 1 gates + update (independent chain)
            {
                float gi = tb1.x + (lo2(a10) + hi2(a10));
                float gf = tb1.y + (lo2(a11) + hi2(a11));
                float gg = tb1.z + (lo2(a12) + hi2(a12));
                float go = tb1.w + (lo2(a13) + hi2(a13));
                float is = sigmoid_fast(gi);
                float fs = sigmoid_fast(gf);
                float os = sigmoid_fast(go);
                float gt = tanh_fast(gg);
                c1 = fmaf(fs, c1, is * gt);
                h1 = os * tanh_fast(c1);
            }

            // broadcast new h vectors through shared memory
            ((float*)hbuf[wid][0])[lane] = h0;
            ((float*)hbuf[wid][1])[lane] = h1;
            __syncwarp();
            #pragma unroll
            for (int q = 0; q < 8; ++q) {
                hv0[q] = hbuf[wid][0][q];   // broadcast LDS.128
                hv1[q] = hbuf[wid][1][q];
            }
        }
    }

    // FC head for both rows (warp butterfly reduce, 2 outputs each)
    float wf0 = Wfc[lane * 2 + 0], wf1 = Wfc[lane * 2 + 1];
    float u0 = h0 * wf0, u1 = h0 * wf1;
    float v0 = h1 * wf0, v1 = h1 * wf1;
    #pragma unroll
    for (int o = 16; o; o >>= 1) {
        u0 += __shfl_xor_sync(FULL, u0, o);
        u1 += __shfl_xor_sync(FULL, u1, o);
        v0 += __shfl_xor_sync(FULL, v0, o);
        v1 += __shfl_xor_sync(FULL, v1, o);
    }
    if (lane == 0) {
        out[b0 * 2 + 0] = u0 + bfc[0];
        out[b0 * 2 + 1] = u1 + bfc[1];
        out[b0 * 2 + 2] = v0 + bfc[0];
        out[b0 * 2 + 3] = v1 + bfc[1];
    }
}

// ---------------------------------------------------------------------------
// Harness entry
// Inputs: x[int32 B*T], emb[101*32], Wx[32*128], Wh[32*128], b[128],
//         W_fc[32*2], b_fc[2]. Output: float [B,2].
// ---------------------------------------------------------------------------
extern "C" void kernel_launch(void* const* d_in, const int* in_sizes, int n_in,
                              void* d_out, int out_size) {
    const int*   x   = (const int*)  d_in[0];
    const float* emb = (const float*)d_in[1];
    const float* Wx  = (const float*)d_in[2];
    const float* Wh  = (const float*)d_in[3];
    const float* b   = (const float*)d_in[4];
    const float* Wfc = (const float*)d_in[5];
    const float* bfc = (const float*)d_in[6];
    float* out = (float*)d_out;

    const int B = in_sizes[0] / T_STEPS;

    prep_kernel<<<(VOCAB * HID + 255) / 256, 256>>>(emb, Wx, b, Wh);

    const int rows_per_block = 2 * NWARP;
    const int blocks = (B + rows_per_block - 1) / rows_per_block;
    lstm_kernel<<<blocks, NWARP * 32>>>(x, Wfc, bfc, out, B);
}

// round 8
// speedup vs baseline: 1.6075x; 1.1135x over previous
#include <cuda_runtime.h>

#define VOCAB   101
#define EMB     32
#define HID     32
#define T_STEPS 512
#define NWARP   8   // warps per block
#define RPW     4   // batch rows per warp

// Precomputed per-token gate contributions: tbl[v][j] = (i, f, g, o)
__device__ float4 g_tbl[VOCAB * HID];
// Packed recurrence weights (f32x2 across k):
// g_wpk[(gate*16 + k2)*32 + j] = ( Wh[2*k2][gate*32+j], Wh[2*k2+1][gate*32+j] )
__device__ unsigned long long g_wpk[4 * 16 * 32];

__device__ __forceinline__ unsigned long long pack2(float lo, float hi) {
    unsigned long long r;
    asm("mov.b64 %0, {%1, %2};" : "=l"(r) : "f"(lo), "f"(hi));
    return r;
}
__device__ __forceinline__ float lo2(unsigned long long v) {
    return __uint_as_float((unsigned int)v);
}
__device__ __forceinline__ float hi2(unsigned long long v) {
    return __uint_as_float((unsigned int)(v >> 32));
}
// Packed double-rate fp32 FMA (Blackwell FFMA2)
__device__ __forceinline__ unsigned long long ffma2(unsigned long long a,
                                                    unsigned long long b,
                                                    unsigned long long c) {
    unsigned long long d;
    asm("fma.rn.f32x2 %0, %1, %2, %3;" : "=l"(d) : "l"(a), "l"(b), "l"(c));
    return d;
}
// HW tanh (MUFU.TANH)
__device__ __forceinline__ float tanh_fast(float x) {
    float y;
    asm("tanh.approx.f32 %0, %1;" : "=f"(y) : "f"(x));
    return y;
}
__device__ __forceinline__ float sigmoid_fast(float x) {
    return fmaf(0.5f, tanh_fast(0.5f * x), 0.5f);
}

// ---------------------------------------------------------------------------
// Prep: token->xgate table and packed Wh. Tiny.
// ---------------------------------------------------------------------------
__global__ void prep_kernel(const float* __restrict__ emb,
                            const float* __restrict__ Wx,
                            const float* __restrict__ b,
                            const float* __restrict__ Wh) {
    int tid = blockIdx.x * blockDim.x + threadIdx.x;
    if (tid < VOCAB * HID) {
        int v = tid / HID, j = tid % HID;
        float si = b[j], sf = b[HID + j], sg = b[2 * HID + j], so = b[3 * HID + j];
        #pragma unroll
        for (int e = 0; e < EMB; e++) {
            float xe = emb[v * EMB + e];
            si = fmaf(xe, Wx[e * 4 * HID + j], si);
            sf = fmaf(xe, Wx[e * 4 * HID + HID + j], sf);
            sg = fmaf(xe, Wx[e * 4 * HID + 2 * HID + j], sg);
            so = fmaf(xe, Wx[e * 4 * HID + 3 * HID + j], so);
        }
        g_tbl[tid] = make_float4(si, sf, sg, so);
    }
    if (tid < 4 * 16 * 32) {
        int j  = tid & 31;
        int k2 = (tid >> 5) & 15;
        int g  = tid >> 9;
        float w0 = Wh[(2 * k2) * 4 * HID + g * HID + j];
        float w1 = Wh[(2 * k2 + 1) * 4 * HID + g * HID + j];
        g_wpk[tid] = pack2(w0, w1);
    }
}

// ---------------------------------------------------------------------------
// Main: one warp handles FOUR batch rows. Lane j owns hidden unit j of each
// row. h lives in ping-pong shared buffers; the matvec reads h pairs via
// broadcast LDS.64 (pre-packed for f32x2), weights stay in registers.
// Grid = 128 blocks -> single wave on 148 SMs.
// ---------------------------------------------------------------------------
__global__ void __launch_bounds__(NWARP * 32, 1)
lstm_kernel(const int* __restrict__ x,
            const float* __restrict__ Wfc,
            const float* __restrict__ bfc,
            float* __restrict__ out, int B) {
    const unsigned FULL = 0xffffffffu;
    const int lane = threadIdx.x & 31;
    const int wid  = threadIdx.x >> 5;
    const int b0 = (int)(blockIdx.x * NWARP + wid) * RPW;
    if (b0 >= B) return;

    // ping-pong h buffers: [warp][parity][row][unit]
    __shared__ __align__(16) float hsm[NWARP][2][RPW][HID];

    // 64 packed weight words (128 fp32), shared by all 4 rows
    unsigned long long w[64];
    #pragma unroll
    for (int i = 0; i < 64; i++) w[i] = g_wpk[i * 32 + lane];

    // init read-buffer 0 to zeros
    #pragma unroll
    for (int r = 0; r < RPW; ++r) hsm[wid][0][r][lane] = 0.f;
    __syncwarp();

    float c[RPW], hlast[RPW];
    #pragma unroll
    for (int r = 0; r < RPW; ++r) { c[r] = 0.f; hlast[r] = 0.f; }

    const int* xrow[RPW];
    #pragma unroll
    for (int r = 0; r < RPW; ++r) {
        int bb = b0 + r; if (bb >= B) bb = B - 1;
        xrow[r] = x + (long long)bb * T_STEPS;
    }

    for (int tc = 0; tc < T_STEPS / 32; ++tc) {
        int tokr[RPW];
        #pragma unroll
        for (int r = 0; r < RPW; ++r) tokr[r] = xrow[r][tc * 32 + lane];

        #pragma unroll 2
        for (int s = 0; s < 32; ++s) {
            const int buf = s & 1;

            // table loads first: LDG latency hides under the FMA loop
            float4 tb[RPW];
            #pragma unroll
            for (int r = 0; r < RPW; ++r) {
                int tok = __shfl_sync(FULL, tokr[r], s);
                tb[r] = __ldg(&g_tbl[tok * HID + lane]);
            }

            const unsigned long long* hp[RPW];
            #pragma unroll
            for (int r = 0; r < RPW; ++r)
                hp[r] = (const unsigned long long*)hsm[wid][buf][r];

            unsigned long long acc[RPW][4];
            #pragma unroll
            for (int r = 0; r < RPW; ++r)
                acc[r][0] = acc[r][1] = acc[r][2] = acc[r][3] = 0ull;

            #pragma unroll
            for (int k2 = 0; k2 < 16; ++k2) {
                #pragma unroll
                for (int r = 0; r < RPW; ++r) {
                    unsigned long long hk = hp[r][k2];   // broadcast LDS.64
                    acc[r][0] = ffma2(hk, w[     k2], acc[r][0]);
                    acc[r][1] = ffma2(hk, w[16 + k2], acc[r][1]);
                    acc[r][2] = ffma2(hk, w[32 + k2], acc[r][2]);
                    acc[r][3] = ffma2(hk, w[48 + k2], acc[r][3]);
                }
            }

            #pragma unroll
            for (int r = 0; r < RPW; ++r) {
                float gi = tb[r].x + (lo2(acc[r][0]) + hi2(acc[r][0]));
                float gf = tb[r].y + (lo2(acc[r][1]) + hi2(acc[r][1]));
                float gg = tb[r].z + (lo2(acc[r][2]) + hi2(acc[r][2]));
                float go = tb[r].w + (lo2(acc[r][3]) + hi2(acc[r][3]));
                float is = sigmoid_fast(gi);
                float fs = sigmoid_fast(gf);
                float os = sigmoid_fast(go);
                float gt = tanh_fast(gg);
                c[r] = fmaf(fs, c[r], is * gt);
                float h = os * tanh_fast(c[r]);
                hlast[r] = h;
                hsm[wid][buf ^ 1][r][lane] = h;   // write next-step buffer
            }
            __syncwarp();
        }
    }

    // FC head: out[b] = h @ W_fc + b_fc per row (warp butterfly reduce)
    float wf0 = Wfc[lane * 2 + 0], wf1 = Wfc[lane * 2 + 1];
    #pragma unroll
    for (int r = 0; r < RPW; ++r) {
        float u0 = hlast[r] * wf0;
        float u1 = hlast[r] * wf1;
        #pragma unroll
        for (int o = 16; o; o >>= 1) {
            u0 += __shfl_xor_sync(FULL, u0, o);
            u1 += __shfl_xor_sync(FULL, u1, o);
        }
        if (lane == 0 && b0 + r < B) {
            out[(b0 + r) * 2 + 0] = u0 + bfc[0];
            out[(b0 + r) * 2 + 1] = u1 + bfc[1];
        }
    }
}

// ---------------------------------------------------------------------------
// Harness entry
// Inputs: x[int32 B*T], emb[101*32], Wx[32*128], Wh[32*128], b[128],
//         W_fc[32*2], b_fc[2]. Output: float [B,2].
// ---------------------------------------------------------------------------
extern "C" void kernel_launch(void* const* d_in, const int* in_sizes, int n_in,
                              void* d_out, int out_size) {
    const int*   x   = (const int*)  d_in[0];
    const float* emb = (const float*)d_in[1];
    const float* Wx  = (const float*)d_in[2];
    const float* Wh  = (const float*)d_in[3];
    const float* b   = (const float*)d_in[4];
    const float* Wfc = (const float*)d_in[5];
    const float* bfc = (const float*)d_in[6];
    float* out = (float*)d_out;

    const int B = in_sizes[0] / T_STEPS;

    prep_kernel<<<(VOCAB * HID + 255) / 256, 256>>>(emb, Wx, b, Wh);

    const int rows_per_block = RPW * NWARP;   // 32
    const int blocks = (B + rows_per_block - 1) / rows_per_block;  // 128
    lstm_kernel<<<blocks, NWARP * 32>>>(x, Wfc, bfc, out, B);
}